// round 2
// baseline (speedup 1.0000x reference)
#include <cuda_runtime.h>
#include <math.h>

#define BB 4
#define CC 1024
#define TT 4096
#define HH 16
#define DD 64
#define BT (BB*TT)        // 16384
#define SPLIT 8
#define TCH (TT/SPLIT)    // 512

// Scratch (alloc-free: __device__ globals)
__device__ float g_q[(size_t)BT*CC];
__device__ float g_k[(size_t)BT*CC];
__device__ float g_v[(size_t)BT*CC];
__device__ float g_attn[(size_t)BT*CC];
__device__ float g_kv[BB*HH*DD*DD];
__device__ float g_ksum[BB*HH*DD];

// ---------------------------------------------------------------------------
// QKV projection GEMM: out[bt, n] = act( sum_k xt[bt,k] * W[n,k] + bias[n] )
// xt[bt,k] = x[b, k, t]  (b = bt/T, t = bt%T)
// ACT=1: elu(v)+1 = v>0 ? v+1 : exp(v);   ACT=0: identity
// Tiles: 64(M=bt) x 64(N) x 16(K), 256 threads, 4x4 microtile
// ---------------------------------------------------------------------------
template<int ACT>
__global__ void proj_kernel(const float* __restrict__ x, const float* __restrict__ W,
                            const float* __restrict__ bias, float* __restrict__ out)
{
    __shared__ float As[16][65];
    __shared__ float Bs[16][65];
    const int bm = blockIdx.x * 64;   // bt tile origin (never crosses batch: T%64==0)
    const int bn = blockIdx.y * 64;
    const int b  = bm / TT;
    const int t0 = bm % TT;
    const int tid = threadIdx.x;
    const int tx = tid & 15, ty = tid >> 4;
    float acc[4][4] = {};
    const float* xb = x + (size_t)b * CC * TT + t0;

    for (int k0 = 0; k0 < CC; k0 += 16) {
        #pragma unroll
        for (int r = 0; r < 4; r++) {               // A: coalesced over t
            int i = tid + r*256;
            int kk = i >> 6, m = i & 63;
            As[kk][m] = xb[(size_t)(k0+kk)*TT + m];
        }
        #pragma unroll
        for (int r = 0; r < 4; r++) {               // B: 64B segments along k
            int i = tid + r*256;
            int kk = i & 15, n = i >> 4;
            Bs[kk][n] = W[(size_t)(bn+n)*CC + k0 + kk];
        }
        __syncthreads();
        #pragma unroll
        for (int kk = 0; kk < 16; kk++) {
            float a[4], bb[4];
            #pragma unroll
            for (int i = 0; i < 4; i++) a[i]  = As[kk][ty*4+i];
            #pragma unroll
            for (int j = 0; j < 4; j++) bb[j] = Bs[kk][tx*4+j];
            #pragma unroll
            for (int i = 0; i < 4; i++)
                #pragma unroll
                for (int j = 0; j < 4; j++)
                    acc[i][j] = fmaf(a[i], bb[j], acc[i][j]);
        }
        __syncthreads();
    }

    #pragma unroll
    for (int i = 0; i < 4; i++) {
        int m = bm + ty*4 + i;
        #pragma unroll
        for (int j = 0; j < 4; j++) {
            int n = bn + tx*4 + j;
            float v = acc[i][j] + bias[n];
            if (ACT) v = (v > 0.f) ? (v + 1.f) : expf(v);
            out[(size_t)m*CC + n] = v;
        }
    }
}

// ---------------------------------------------------------------------------
// Zero the kv / ksum accumulators (graph replays require re-zeroing each call)
// ---------------------------------------------------------------------------
__global__ void zero_kernel()
{
    int i = blockIdx.x * 256 + threadIdx.x;
    if (i < BB*HH*DD*DD) g_kv[i] = 0.f;
    if (i < BB*HH*DD)    g_ksum[i] = 0.f;
}

// ---------------------------------------------------------------------------
// kv[b,h,d,e] = sum_t k[b,t,h,d] * v[b,t,h,e];  ksum[b,h,d] = sum_t k[b,t,h,d]
// grid = B*H*SPLIT blocks, 256 threads. Each block reduces a T-chunk of 512,
// atomically merging into the global accumulators.
// thread owns (d = tid/4, e in [(tid&3)*16, +16))  → 16 accumulators
// ---------------------------------------------------------------------------
__global__ void kv_kernel()
{
    __shared__ float Ks[32][64];
    __shared__ float Vs[32][64];
    const int blk = blockIdx.x;
    const int sp  = blk & (SPLIT-1);
    const int bh  = blk / SPLIT;
    const int b = bh / HH, h = bh % HH;
    const int tid = threadIdx.x;
    const int d  = tid >> 2;
    const int e0 = (tid & 3) * 16;
    float acc[16] = {};
    float ks_local = 0.f;
    const size_t base = (size_t)(b*TT + sp*TCH) * CC + h*DD;

    for (int t0 = 0; t0 < TCH; t0 += 32) {
        #pragma unroll
        for (int r = 0; r < 8; r++) {
            int i = tid + r*256;
            int ttl = i >> 6, dd2 = i & 63;
            size_t g = base + (size_t)(t0+ttl)*CC + dd2;
            Ks[ttl][dd2] = g_k[g];
            Vs[ttl][dd2] = g_v[g];
        }
        __syncthreads();
        #pragma unroll
        for (int ttl = 0; ttl < 32; ttl++) {
            float kvv = Ks[ttl][d];
            #pragma unroll
            for (int j = 0; j < 16; j++)
                acc[j] = fmaf(kvv, Vs[ttl][e0+j], acc[j]);
        }
        if (tid < 64) {
            #pragma unroll
            for (int ttl = 0; ttl < 32; ttl++) ks_local += Ks[ttl][tid];
        }
        __syncthreads();
    }

    float* kvout = &g_kv[(size_t)((b*HH+h)*DD + d)*DD];
    #pragma unroll
    for (int j = 0; j < 16; j++) atomicAdd(&kvout[e0+j], acc[j]);
    if (tid < 64) atomicAdd(&g_ksum[(b*HH+h)*DD + tid], ks_local);
}

// ---------------------------------------------------------------------------
// attn[bt, h*64+e] = (sum_d q[bt,h,d]*kv[b,h,d,e]) / (sum_d q[bt,h,d]*ksum[b,h,d] + 1e-6)
// One block per bt. kv (1 MB per full tensor) stays L2-resident.
// ---------------------------------------------------------------------------
__global__ void attn_kernel()
{
    __shared__ float qs[CC];
    __shared__ float zr[HH];
    const int bt = blockIdx.x;
    const int b  = bt / TT;
    const int tid = threadIdx.x;

    #pragma unroll
    for (int r = 0; r < 4; r++)
        qs[tid + r*256] = g_q[(size_t)bt*CC + tid + r*256];
    __syncthreads();

    if (tid < HH) {
        float z = 0.f;
        const float* ks = &g_ksum[(b*HH + tid)*DD];
        #pragma unroll
        for (int dd = 0; dd < DD; dd++) z = fmaf(qs[tid*DD+dd], ks[dd], z);
        zr[tid] = 1.f / (z + 1e-6f);
    }
    __syncthreads();

    #pragma unroll
    for (int r = 0; r < 4; r++) {
        int o = tid + r*256;
        int h = o >> 6, e = o & 63;
        const float* kvp = &g_kv[(size_t)((b*HH+h)*DD)*DD + e];
        const float* qp  = &qs[h*DD];
        float acc = 0.f;
        #pragma unroll
        for (int dd = 0; dd < DD; dd++)
            acc = fmaf(qp[dd], kvp[dd*DD], acc);     // coalesced over e across lanes
        g_attn[(size_t)bt*CC + o] = acc * zr[h];
    }
}

// ---------------------------------------------------------------------------
// Output projection + bias + residual + transpose:
// out[b, n, t] = sum_k attn[bt,k]*Wo[n,k] + bo[n] + x[b, n, t]
// ---------------------------------------------------------------------------
__global__ void out_kernel(const float* __restrict__ x, const float* __restrict__ Wo,
                           const float* __restrict__ bo, float* __restrict__ out)
{
    __shared__ float As[16][65];
    __shared__ float Bs[16][65];
    const int bm = blockIdx.x * 64;   // bt tile
    const int bn = blockIdx.y * 64;   // output channel tile
    const int b  = bm / TT;
    const int t0 = bm % TT;
    const int tid = threadIdx.x;
    const int tx = tid & 15, ty = tid >> 4;
    float acc[4][4] = {};

    for (int k0 = 0; k0 < CC; k0 += 16) {
        #pragma unroll
        for (int r = 0; r < 4; r++) {               // A: attn is [bt, C] row-major
            int i = tid + r*256;
            int kk = i & 15, m = i >> 4;
            As[kk][m] = g_attn[(size_t)(bm+m)*CC + k0 + kk];
        }
        #pragma unroll
        for (int r = 0; r < 4; r++) {
            int i = tid + r*256;
            int kk = i & 15, n = i >> 4;
            Bs[kk][n] = Wo[(size_t)(bn+n)*CC + k0 + kk];
        }
        __syncthreads();
        #pragma unroll
        for (int kk = 0; kk < 16; kk++) {
            float a[4], bb[4];
            #pragma unroll
            for (int i = 0; i < 4; i++) a[i]  = As[kk][ty*4+i];
            #pragma unroll
            for (int j = 0; j < 4; j++) bb[j] = Bs[kk][tx*4+j];
            #pragma unroll
            for (int i = 0; i < 4; i++)
                #pragma unroll
                for (int j = 0; j < 4; j++)
                    acc[i][j] = fmaf(a[i], bb[j], acc[i][j]);
        }
        __syncthreads();
    }

    #pragma unroll
    for (int j = 0; j < 4; j++) {
        int n = bn + tx*4 + j;
        float bn_bias = bo[n];
        #pragma unroll
        for (int i = 0; i < 4; i++) {
            int m = ty*4 + i;
            size_t idx = (size_t)b*CC*TT + (size_t)n*TT + t0 + m;
            out[idx] = acc[i][j] + bn_bias + x[idx];
        }
    }
}

// ---------------------------------------------------------------------------
extern "C" void kernel_launch(void* const* d_in, const int* in_sizes, int n_in,
                              void* d_out, int out_size)
{
    const float* x  = (const float*)d_in[0];
    const float* Wq = (const float*)d_in[1];
    const float* bq = (const float*)d_in[2];
    const float* Wk = (const float*)d_in[3];
    const float* bk = (const float*)d_in[4];
    const float* Wv = (const float*)d_in[5];
    const float* bv = (const float*)d_in[6];
    const float* Wo = (const float*)d_in[7];
    const float* bo = (const float*)d_in[8];
    float* out = (float*)d_out;

    float *gq, *gk, *gv;
    cudaGetSymbolAddress((void**)&gq, g_q);
    cudaGetSymbolAddress((void**)&gk, g_k);
    cudaGetSymbolAddress((void**)&gv, g_v);

    dim3 grid(BT/64, CC/64);
    proj_kernel<1><<<grid, 256>>>(x, Wq, bq, gq);
    proj_kernel<1><<<grid, 256>>>(x, Wk, bk, gk);
    proj_kernel<0><<<grid, 256>>>(x, Wv, bv, gv);
    zero_kernel<<<(BB*HH*DD*DD + 255)/256, 256>>>();
    kv_kernel<<<BB*HH*SPLIT, 256>>>();
    attn_kernel<<<BT, 256>>>();
    out_kernel<<<grid, 256>>>(x, Wo, bo, out);
}

// round 4
// speedup vs baseline: 4.0384x; 4.0384x over previous
#include <cuda_runtime.h>
#include <math.h>
#include <stdint.h>

#define BB 4
#define CC 1024
#define TT 4096
#define HH 16
#define DD 64
#define BT (BB*TT)        // 16384
#define SPLIT 8
#define TCH (TT/SPLIT)    // 512

// ---------------- scratch (alloc-free: __device__ globals) ----------------
__device__ float g_xt[(size_t)BT*CC];      // x transposed, tf32-rounded
__device__ float g_q [(size_t)BT*CC];
__device__ float g_k [(size_t)BT*CC];
__device__ float g_v [(size_t)BT*CC];
__device__ float g_attn[(size_t)BT*CC];    // tf32-rounded
__device__ float g_w [(size_t)4*CC*CC];    // tf32-rounded Wq,Wk,Wv,Wo
__device__ float g_kv[BB*HH*DD*DD];
__device__ float g_ksum[BB*HH*DD];

// ---------------- helpers ----------------
__device__ __forceinline__ uint32_t smem_u32(const void* p){
    uint32_t a;
    asm("{ .reg .u64 t; cvta.to.shared.u64 t, %1; cvt.u32.u64 %0, t; }" : "=r"(a) : "l"(p));
    return a;
}
__device__ __forceinline__ float rn_tf32(float x){
    uint32_t u; asm("cvt.rn.tf32.f32 %0, %1;" : "=r"(u) : "f"(x));
    return __uint_as_float(u);
}

#define CP_ASYNC16(saddr, gptr) \
    asm volatile("cp.async.cg.shared.global [%0], [%1], 16;" :: "r"(saddr), "l"(gptr))
#define CP_COMMIT() asm volatile("cp.async.commit_group;" ::: "memory")
#define CP_WAIT1()  asm volatile("cp.async.wait_group 1;" ::: "memory")
#define CP_WAIT0()  asm volatile("cp.async.wait_group 0;" ::: "memory")

// m16n8k8 tf32 mma (portable, sm_80+): D = A(16x8,row) * B(8x8,col == B^T row-major [n][k]) + D
__device__ __forceinline__ void mma_tf32(float* c, const float* a, const float* b){
    asm volatile("mma.sync.aligned.m16n8k8.row.col.f32.tf32.tf32.f32 "
        "{%0,%1,%2,%3}, {%4,%5,%6,%7}, {%8,%9}, {%0,%1,%2,%3};"
        : "+f"(c[0]), "+f"(c[1]), "+f"(c[2]), "+f"(c[3])
        : "r"(__float_as_uint(a[0])), "r"(__float_as_uint(a[1])),
          "r"(__float_as_uint(a[2])), "r"(__float_as_uint(a[3])),
          "r"(__float_as_uint(b[0])), "r"(__float_as_uint(b[1])));
}

// ---------------- GEMM SMEM layout ----------------
// A/B tiles: 128 rows x 32 floats, row stride 36 floats (conflict-free frag fetch)
#define TS 36
#define STAGE_F (128*TS)                 // floats per operand tile
// layout: [A0 | B0 | A1 | B1], total 4*STAGE_F floats = 73728 B
#define GEMM_SMEM_BYTES (4*STAGE_F*4)
#define NKCH 32

// ---------------------------------------------------------------------------
// tf32 tensor-core GEMM: D[m,n] = sum_k A[m,k]*Bw[n,k]
// block tile 128x128, warp tile 64x32 (2x4 warps), K chunk 32 (4 x k8)
// MODE 0: out[m*CC+n] = D + bias[n]
// MODE 1: out[m*CC+n] = elu(D + bias[n]) + 1
// MODE 2: out[b,n,t]  = D + bias[n] + resid[b,n,t]   (m = b*TT + t)
// ---------------------------------------------------------------------------
template<int MODE>
__global__ void __launch_bounds__(256, 2)
gemm_mma(const float* __restrict__ A, const float* __restrict__ Bw,
         const float* __restrict__ bias, const float* __restrict__ resid,
         float* __restrict__ out)
{
    extern __shared__ float sm[];
    const uint32_t su = smem_u32(sm);
    const int tid  = threadIdx.x;
    const int wid  = tid >> 5, lane = tid & 31;
    const int g    = lane >> 2, t4 = lane & 3;
    const int wm   = wid >> 2,  wn  = wid & 3;
    const int bm   = blockIdx.x * 128;
    const int bn   = blockIdx.y * 128;

    const float* Ab = A  + (size_t)bm * CC;
    const float* Bb = Bw + (size_t)bn * CC;

    float acc[4][4][4];
    #pragma unroll
    for (int i = 0; i < 4; i++)
        #pragma unroll
        for (int j = 0; j < 4; j++)
            #pragma unroll
            for (int e = 0; e < 4; e++) acc[i][j][e] = 0.f;

    // stage offsets in floats
    const int offA[2] = {0,            2*STAGE_F};
    const int offB[2] = {STAGE_F,      3*STAGE_F};

    // ---- async tile loader: 128 rows x 32 floats each for A and B ----
    auto load_stage = [&](int st, int kc){
        const float* a = Ab + kc*32;
        const float* b = Bb + kc*32;
        #pragma unroll
        for (int r = 0; r < 4; r++){
            int i = tid + r*256;           // 1024 16B transfers per operand
            int row = i >> 3, cq = i & 7;
            CP_ASYNC16(su + (uint32_t)(offA[st] + row*TS + cq*4)*4,
                       a + (size_t)row*CC + cq*4);
            CP_ASYNC16(su + (uint32_t)(offB[st] + row*TS + cq*4)*4,
                       b + (size_t)row*CC + cq*4);
        }
    };

    load_stage(0, 0); CP_COMMIT();

    for (int kc = 0; kc < NKCH; kc++){
        const int cur = kc & 1;
        if (kc + 1 < NKCH){
            load_stage(cur ^ 1, kc + 1);
            CP_COMMIT();
            CP_WAIT1();
        } else {
            CP_WAIT0();
        }
        __syncthreads();

        const float* sa = sm + offA[cur];
        const float* sb = sm + offB[cur];
        #pragma unroll
        for (int s = 0; s < 4; s++){
            float ar[4][4], br[4][2];
            #pragma unroll
            for (int mf = 0; mf < 4; mf++){
                int r0 = wm*64 + mf*16 + g;
                ar[mf][0] = sa[ r0     *TS + s*8 + t4    ];
                ar[mf][1] = sa[(r0+8)  *TS + s*8 + t4    ];
                ar[mf][2] = sa[ r0     *TS + s*8 + t4 + 4];
                ar[mf][3] = sa[(r0+8)  *TS + s*8 + t4 + 4];
            }
            #pragma unroll
            for (int nf = 0; nf < 4; nf++){
                int c0 = wn*32 + nf*8 + g;
                br[nf][0] = sb[c0*TS + s*8 + t4    ];
                br[nf][1] = sb[c0*TS + s*8 + t4 + 4];
            }
            #pragma unroll
            for (int mf = 0; mf < 4; mf++)
                #pragma unroll
                for (int nf = 0; nf < 4; nf++)
                    mma_tf32(acc[mf][nf], ar[mf], br[nf]);
        }
        __syncthreads();
    }

    // ---- epilogue ----
    #pragma unroll
    for (int mf = 0; mf < 4; mf++){
        const int m0 = bm + wm*64 + mf*16 + g;
        #pragma unroll
        for (int nf = 0; nf < 4; nf++){
            const int n0 = bn + wn*32 + nf*8 + t4*2;
            const float b0 = bias[n0], b1 = bias[n0+1];
            float v00 = acc[mf][nf][0] + b0;
            float v01 = acc[mf][nf][1] + b1;
            float v10 = acc[mf][nf][2] + b0;
            float v11 = acc[mf][nf][3] + b1;
            if (MODE == 1){
                v00 = (v00 > 0.f) ? (v00 + 1.f) : expf(v00);
                v01 = (v01 > 0.f) ? (v01 + 1.f) : expf(v01);
                v10 = (v10 > 0.f) ? (v10 + 1.f) : expf(v10);
                v11 = (v11 > 0.f) ? (v11 + 1.f) : expf(v11);
            }
            if (MODE == 2){
                const int b  = m0 / TT;
                const int t  = m0 % TT;          // m0+8 same batch (tiles never cross)
                size_t i00 = (size_t)b*CC*TT + (size_t)n0*TT + t;
                size_t i01 = i00 + TT;
                out[i00]     = v00 + resid[i00];
                out[i01]     = v01 + resid[i01];
                out[i00 + 8] = v10 + resid[i00 + 8];
                out[i01 + 8] = v11 + resid[i01 + 8];
            } else {
                float2 lo = make_float2(v00, v01);
                float2 hi = make_float2(v10, v11);
                *(float2*)(out + (size_t) m0    *CC + n0) = lo;
                *(float2*)(out + (size_t)(m0+8) *CC + n0) = hi;
            }
        }
    }
}

// ---------------------------------------------------------------------------
// x[b,c,t] -> g_xt[b*T+t, c], RN-rounded to tf32
// ---------------------------------------------------------------------------
__global__ void transpose_round_kernel(const float* __restrict__ x)
{
    __shared__ float tile[32][33];
    const int t0 = blockIdx.x * 32;
    const int c0 = blockIdx.y * 32;
    const int b  = blockIdx.z;
    const int tx = threadIdx.x, ty = threadIdx.y;
    tile[ty][tx] = x[(size_t)b*CC*TT + (size_t)(c0+ty)*TT + t0 + tx];
    __syncthreads();
    g_xt[(size_t)(b*TT + t0 + ty)*CC + c0 + tx] = rn_tf32(tile[tx][ty]);
}

__global__ void round_w_kernel(const float* __restrict__ w, float* __restrict__ dst)
{
    int i = blockIdx.x * 256 + threadIdx.x;
    dst[i] = rn_tf32(w[i]);
}

__global__ void zero_kernel()
{
    int i = blockIdx.x * 256 + threadIdx.x;
    if (i < BB*HH*DD*DD) g_kv[i] = 0.f;
    if (i < BB*HH*DD)    g_ksum[i] = 0.f;
}

// ---------------------------------------------------------------------------
// kv[b,h,d,e] = sum_t k[b,t,h,d]*v[b,t,h,e];  ksum[b,h,d] = sum_t k
// ---------------------------------------------------------------------------
__global__ void kv_kernel()
{
    __shared__ float Ks[32][64];
    __shared__ float Vs[32][64];
    const int blk = blockIdx.x;
    const int sp  = blk & (SPLIT-1);
    const int bh  = blk / SPLIT;
    const int b = bh / HH, h = bh % HH;
    const int tid = threadIdx.x;
    const int d  = tid >> 2;
    const int e0 = (tid & 3) * 16;
    float acc[16] = {};
    float ks_local = 0.f;
    const size_t base = (size_t)(b*TT + sp*TCH) * CC + h*DD;

    for (int t0 = 0; t0 < TCH; t0 += 32) {
        #pragma unroll
        for (int r = 0; r < 8; r++) {
            int i = tid + r*256;
            int ttl = i >> 6, dd2 = i & 63;
            size_t gg = base + (size_t)(t0+ttl)*CC + dd2;
            Ks[ttl][dd2] = g_k[gg];
            Vs[ttl][dd2] = g_v[gg];
        }
        __syncthreads();
        #pragma unroll
        for (int ttl = 0; ttl < 32; ttl++) {
            float kvv = Ks[ttl][d];
            #pragma unroll
            for (int j = 0; j < 16; j++)
                acc[j] = fmaf(kvv, Vs[ttl][e0+j], acc[j]);
        }
        if (tid < 64) {
            #pragma unroll
            for (int ttl = 0; ttl < 32; ttl++) ks_local += Ks[ttl][tid];
        }
        __syncthreads();
    }

    float* kvout = &g_kv[(size_t)((b*HH+h)*DD + d)*DD];
    #pragma unroll
    for (int j = 0; j < 16; j++) atomicAdd(&kvout[e0+j], acc[j]);
    if (tid < 64) atomicAdd(&g_ksum[(b*HH+h)*DD + tid], ks_local);
}

// ---------------------------------------------------------------------------
// attn: one block per (b, h, 256-t chunk). kv slab (64x64) loaded to SMEM once.
// attn[bt, h*64+e] = (q[bt,h,:]·kv[b,h,:,e]) / (q[bt,h,:]·ksum[b,h,:] + 1e-6)
// ---------------------------------------------------------------------------
#define ATCH 256
__global__ void __launch_bounds__(256) attn_kernel()
{
    __shared__ float kvs[64][65];
    __shared__ float qs[64][65];
    __shared__ float ksums[64];
    __shared__ float zs[64];
    const int blk = blockIdx.x;
    const int tc  = blk % (TT/ATCH);
    const int bh  = blk / (TT/ATCH);
    const int b = bh / HH, h = bh % HH;
    const int tid = threadIdx.x;

    // load kv slab + ksum
    #pragma unroll
    for (int r = 0; r < 16; r++){
        int i = tid + r*256;
        int d = i >> 6, e = i & 63;
        kvs[d][e] = g_kv[(size_t)((b*HH+h)*DD + d)*DD + e];
    }
    if (tid < 64) ksums[tid] = g_ksum[(b*HH+h)*DD + tid];
    __syncthreads();

    const int tbase = b*TT + tc*ATCH;
    for (int tt0 = 0; tt0 < ATCH; tt0 += 64){
        // load 64 q rows (coalesced: 64 floats per row)
        #pragma unroll
        for (int r = 0; r < 16; r++){
            int i = tid + r*256;
            int row = i >> 6, col = i & 63;
            qs[row][col] = g_q[(size_t)(tbase + tt0 + row)*CC + h*DD + col];
        }
        __syncthreads();
        if (tid < 64){
            float z = 0.f;
            #pragma unroll
            for (int d = 0; d < 64; d++) z = fmaf(qs[tid][d], ksums[d], z);
            zs[tid] = 1.f / (z + 1e-6f);
        }
        __syncthreads();
        const int e  = tid & 63;
        const int tg = tid >> 6;
        #pragma unroll
        for (int k = 0; k < 16; k++){
            int trow = tg*16 + k;
            float a = 0.f;
            #pragma unroll
            for (int d = 0; d < 64; d++)
                a = fmaf(qs[trow][d], kvs[d][e], a);
            g_attn[(size_t)(tbase + tt0 + trow)*CC + h*DD + e] = rn_tf32(a * zs[trow]);
        }
        __syncthreads();
    }
}

// ---------------------------------------------------------------------------
extern "C" void kernel_launch(void* const* d_in, const int* in_sizes, int n_in,
                              void* d_out, int out_size)
{
    const float* x  = (const float*)d_in[0];
    const float* Wq = (const float*)d_in[1];
    const float* bq = (const float*)d_in[2];
    const float* Wk = (const float*)d_in[3];
    const float* bk = (const float*)d_in[4];
    const float* Wv = (const float*)d_in[5];
    const float* bv = (const float*)d_in[6];
    const float* Wo = (const float*)d_in[7];
    const float* bo = (const float*)d_in[8];
    float* out = (float*)d_out;

    float *gxt, *gq, *gk, *gv, *gattn, *gw;
    cudaGetSymbolAddress((void**)&gxt,  g_xt);
    cudaGetSymbolAddress((void**)&gq,   g_q);
    cudaGetSymbolAddress((void**)&gk,   g_k);
    cudaGetSymbolAddress((void**)&gv,   g_v);
    cudaGetSymbolAddress((void**)&gattn,g_attn);
    cudaGetSymbolAddress((void**)&gw,   g_w);

    cudaFuncSetAttribute(gemm_mma<0>, cudaFuncAttributeMaxDynamicSharedMemorySize, GEMM_SMEM_BYTES);
    cudaFuncSetAttribute(gemm_mma<1>, cudaFuncAttributeMaxDynamicSharedMemorySize, GEMM_SMEM_BYTES);
    cudaFuncSetAttribute(gemm_mma<2>, cudaFuncAttributeMaxDynamicSharedMemorySize, GEMM_SMEM_BYTES);

    // 1. pack inputs (tf32 rounding)
    transpose_round_kernel<<<dim3(TT/32, CC/32, BB), dim3(32,32)>>>(x);
    round_w_kernel<<<CC*CC/256, 256>>>(Wq, gw + 0*(size_t)CC*CC);
    round_w_kernel<<<CC*CC/256, 256>>>(Wk, gw + 1*(size_t)CC*CC);
    round_w_kernel<<<CC*CC/256, 256>>>(Wv, gw + 2*(size_t)CC*CC);
    round_w_kernel<<<CC*CC/256, 256>>>(Wo, gw + 3*(size_t)CC*CC);

    // 2. Q/K/V projections (tf32 tensor cores)
    dim3 gg(BT/128, CC/128);
    gemm_mma<1><<<gg, 256, GEMM_SMEM_BYTES>>>(gxt, gw + 0*(size_t)CC*CC, bq, nullptr, gq);
    gemm_mma<1><<<gg, 256, GEMM_SMEM_BYTES>>>(gxt, gw + 1*(size_t)CC*CC, bk, nullptr, gk);
    gemm_mma<0><<<gg, 256, GEMM_SMEM_BYTES>>>(gxt, gw + 2*(size_t)CC*CC, bv, nullptr, gv);

    // 3. linear attention
    zero_kernel<<<(BB*HH*DD*DD + 255)/256, 256>>>();
    kv_kernel<<<BB*HH*SPLIT, 256>>>();
    attn_kernel<<<BB*HH*(TT/ATCH), 256>>>();

    // 4. output projection + bias + residual + transpose
    gemm_mma<2><<<gg, 256, GEMM_SMEM_BYTES>>>(gattn, gw + 3*(size_t)CC*CC, bo, x, out);
}

// round 5
// speedup vs baseline: 8.4293x; 2.0873x over previous
#include <cuda_runtime.h>
#include <cuda_bf16.h>
#include <math.h>
#include <stdint.h>

#define BB 4
#define CC 1024
#define TT 4096
#define HH 16
#define DD 64
#define BT (BB*TT)        // 16384
#define KSPLIT 4
#define NKCH 32           // K chunks of 32 per proj GEMM
#define TSB 40            // proj smem row stride (bf16) — conflict-free

// ---------------- scratch (alloc-free: __device__ globals) ----------------
__device__ __nv_bfloat16 g_xt [(size_t)BT*CC];     // xt[bt][c]
__device__ __nv_bfloat16 g_q16[(size_t)BT*CC];     // q[bt][c]
__device__ __nv_bfloat16 g_kt [(size_t)BB*CC*TT];  // k^T[b*CC+c][t]
__device__ __nv_bfloat16 g_vt [(size_t)BB*CC*TT];  // v^T[b*CC+c][t]
__device__ __nv_bfloat16 g_attn16[(size_t)BT*CC];  // attn[bt][c]
__device__ __nv_bfloat16 g_w16[(size_t)4*CC*CC];   // Wq,Wk,Wv,Wo bf16
// kv partials: [split][bh][n(72: 0..63=kv cols e, 64=ksum)][d(64)]
__device__ float g_kvP[KSPLIT][BB*HH][72*64];

// ---------------- helpers ----------------
__device__ __forceinline__ uint32_t smem_u32(const void* p){
    uint32_t a;
    asm("{ .reg .u64 t; cvta.to.shared.u64 t, %1; cvt.u32.u64 %0, t; }" : "=r"(a) : "l"(p));
    return a;
}

#define CP_ASYNC16(saddr, gptr) \
    asm volatile("cp.async.cg.shared.global [%0], [%1], 16;" :: "r"(saddr), "l"(gptr))
#define CP_COMMIT() asm volatile("cp.async.commit_group;" ::: "memory")
#define CP_WAIT1()  asm volatile("cp.async.wait_group 1;" ::: "memory")
#define CP_WAIT0()  asm volatile("cp.async.wait_group 0;" ::: "memory")

// m16n8k16 bf16: D += A(16x16,row) * B(16x8,col: stored [n][k], k contiguous)
__device__ __forceinline__ void mma_bf16(float* c, const uint32_t* a, const uint32_t* b){
    asm volatile("mma.sync.aligned.m16n8k16.row.col.f32.bf16.bf16.f32 "
        "{%0,%1,%2,%3}, {%4,%5,%6,%7}, {%8,%9}, {%0,%1,%2,%3};"
        : "+f"(c[0]), "+f"(c[1]), "+f"(c[2]), "+f"(c[3])
        : "r"(a[0]), "r"(a[1]), "r"(a[2]), "r"(a[3]), "r"(b[0]), "r"(b[1]));
}
__device__ __forceinline__ uint32_t lds32(const __nv_bfloat16* p){
    return *reinterpret_cast<const uint32_t*>(p);
}

// ---------------------------------------------------------------------------
// bf16 tensor-core GEMM: D[m,n] = sum_k A[m,k]*Bw[n,k], block 128x128, warp 64x32
// MODE 1: Q : elu(D+bias)+1 -> bf16 out16[m][CC]
// MODE 3: K : elu(D+bias)+1 -> bf16 transposed out16[(b*CC+n)*TT + t]
// MODE 4: V : D+bias        -> bf16 transposed
// MODE 2: O : D+bias+resid  -> fp32 outf[b][n][t]
// ---------------------------------------------------------------------------
template<int MODE>
__global__ void __launch_bounds__(256)
gemm_bf16(const __nv_bfloat16* __restrict__ A, const __nv_bfloat16* __restrict__ Bw,
          const float* __restrict__ bias, const float* __restrict__ resid,
          float* __restrict__ outf, __nv_bfloat16* __restrict__ out16)
{
    __shared__ __nv_bfloat16 sm[4*128*TSB];
    const uint32_t su = smem_u32(sm);
    const int tid  = threadIdx.x;
    const int wid  = tid >> 5, lane = tid & 31;
    const int g    = lane >> 2, t4 = lane & 3;
    const int wm   = wid >> 2,  wn  = wid & 3;
    const int bm   = blockIdx.x * 128;
    const int bn   = blockIdx.y * 128;

    const __nv_bfloat16* Ab = A  + (size_t)bm * CC;
    const __nv_bfloat16* Bb = Bw + (size_t)bn * CC;

    float acc[4][4][4];
    #pragma unroll
    for (int i = 0; i < 4; i++)
        #pragma unroll
        for (int j = 0; j < 4; j++)
            #pragma unroll
            for (int e = 0; e < 4; e++) acc[i][j][e] = 0.f;

    const int offA[2] = {0,          2*128*TSB};
    const int offB[2] = {128*TSB,    3*128*TSB};

    auto load_stage = [&](int st, int kc){
        const __nv_bfloat16* a = Ab + kc*32;
        const __nv_bfloat16* b = Bb + kc*32;
        #pragma unroll
        for (int r = 0; r < 2; r++){
            int i = tid + r*256;            // 512 x 16B per operand
            int row = i >> 2, cq = i & 3;
            CP_ASYNC16(su + (uint32_t)(offA[st] + row*TSB + cq*8)*2,
                       a + (size_t)row*CC + cq*8);
            CP_ASYNC16(su + (uint32_t)(offB[st] + row*TSB + cq*8)*2,
                       b + (size_t)row*CC + cq*8);
        }
    };

    load_stage(0, 0); CP_COMMIT();

    for (int kc = 0; kc < NKCH; kc++){
        const int cur = kc & 1;
        if (kc + 1 < NKCH){
            load_stage(cur ^ 1, kc + 1);
            CP_COMMIT();
            CP_WAIT1();
        } else {
            CP_WAIT0();
        }
        __syncthreads();

        const __nv_bfloat16* sa = sm + offA[cur];
        const __nv_bfloat16* sb = sm + offB[cur];
        #pragma unroll
        for (int s = 0; s < 2; s++){
            const int kb = s*16 + 2*t4;
            uint32_t ar[4][4], br[4][2];
            #pragma unroll
            for (int mf = 0; mf < 4; mf++){
                int r0 = wm*64 + mf*16 + g;
                ar[mf][0] = lds32(sa +  r0   *TSB + kb);
                ar[mf][1] = lds32(sa + (r0+8)*TSB + kb);
                ar[mf][2] = lds32(sa +  r0   *TSB + kb + 8);
                ar[mf][3] = lds32(sa + (r0+8)*TSB + kb + 8);
            }
            #pragma unroll
            for (int nf = 0; nf < 4; nf++){
                int c0 = wn*32 + nf*8 + g;
                br[nf][0] = lds32(sb + c0*TSB + kb);
                br[nf][1] = lds32(sb + c0*TSB + kb + 8);
            }
            #pragma unroll
            for (int mf = 0; mf < 4; mf++)
                #pragma unroll
                for (int nf = 0; nf < 4; nf++)
                    mma_bf16(acc[mf][nf], ar[mf], br[nf]);
        }
        __syncthreads();
    }

    // ---- epilogue ----
    #pragma unroll
    for (int mf = 0; mf < 4; mf++){
        const int m0 = bm + wm*64 + mf*16 + g;
        #pragma unroll
        for (int nf = 0; nf < 4; nf++){
            const int n0 = bn + wn*32 + nf*8 + t4*2;
            const float b0 = bias[n0], b1 = bias[n0+1];
            float v00 = acc[mf][nf][0] + b0;
            float v01 = acc[mf][nf][1] + b1;
            float v10 = acc[mf][nf][2] + b0;
            float v11 = acc[mf][nf][3] + b1;
            if (MODE == 1 || MODE == 3){
                v00 = (v00 > 0.f) ? (v00 + 1.f) : expf(v00);
                v01 = (v01 > 0.f) ? (v01 + 1.f) : expf(v01);
                v10 = (v10 > 0.f) ? (v10 + 1.f) : expf(v10);
                v11 = (v11 > 0.f) ? (v11 + 1.f) : expf(v11);
            }
            if (MODE == 1){
                *reinterpret_cast<__nv_bfloat162*>(out16 + (size_t) m0   *CC + n0)
                    = __floats2bfloat162_rn(v00, v01);
                *reinterpret_cast<__nv_bfloat162*>(out16 + (size_t)(m0+8)*CC + n0)
                    = __floats2bfloat162_rn(v10, v11);
            } else if (MODE == 3 || MODE == 4){
                const int b = m0 / TT, t = m0 % TT;
                size_t r0i = ((size_t)b*CC + n0)*TT + t;
                size_t r1i = r0i + TT;
                out16[r0i]     = __float2bfloat16_rn(v00);
                out16[r1i]     = __float2bfloat16_rn(v01);
                out16[r0i + 8] = __float2bfloat16_rn(v10);
                out16[r1i + 8] = __float2bfloat16_rn(v11);
            } else { // MODE 2
                const int b = m0 / TT, t = m0 % TT;
                size_t i00 = (size_t)b*CC*TT + (size_t)n0*TT + t;
                size_t i01 = i00 + TT;
                outf[i00]     = v00 + resid[i00];
                outf[i01]     = v01 + resid[i01];
                outf[i00 + 8] = v10 + resid[i00 + 8];
                outf[i01 + 8] = v11 + resid[i01 + 8];
            }
        }
    }
}

// ---------------------------------------------------------------------------
// x[b,c,t] -> g_xt[b*T+t][c] bf16
// ---------------------------------------------------------------------------
__global__ void transpose_round_kernel(const float* __restrict__ x)
{
    __shared__ float tile[32][33];
    const int t0 = blockIdx.x * 32;
    const int c0 = blockIdx.y * 32;
    const int b  = blockIdx.z;
    const int tx = threadIdx.x, ty = threadIdx.y;
    tile[ty][tx] = x[(size_t)b*CC*TT + (size_t)(c0+ty)*TT + t0 + tx];
    __syncthreads();
    g_xt[(size_t)(b*TT + t0 + ty)*CC + c0 + tx] = __float2bfloat16_rn(tile[tx][ty]);
}

__global__ void round_w_kernel(const float* __restrict__ w, __nv_bfloat16* __restrict__ dst)
{
    int i = blockIdx.x * 256 + threadIdx.x;
    dst[i] = __float2bfloat16_rn(w[i]);
}

// ---------------------------------------------------------------------------
// kv via MMA: per (bh, split): A = k^T[d][t] (m=d), B = [v^T; ones][n][t] (n=e|64)
// acc[d][n] += sum_t A*B ; written to private slab g_kvP[sp][bh][n][d]
// ---------------------------------------------------------------------------
__global__ void __launch_bounds__(256) kv_mma_kernel()
{
    __shared__ __nv_bfloat16 sA[2][64*72];
    __shared__ __nv_bfloat16 sB[2][72*72];
    const int blk = blockIdx.x;
    const int sp  = blk % KSPLIT;
    const int bh  = blk / KSPLIT;
    const int b = bh / HH, h = bh % HH;
    const int tid = threadIdx.x;
    const int wid = tid >> 5, lane = tid & 31;
    const int g = lane >> 2, t4 = lane & 3;
    const int wm = wid >> 2, wn = wid & 3;
    const int nt = (wn == 3) ? 3 : 2;

    const uint32_t suA[2] = {smem_u32(sA[0]), smem_u32(sA[1])};
    const uint32_t suB[2] = {smem_u32(sB[0]), smem_u32(sB[1])};

    // persistent ones/zeros rows 64..71 of B (both stages)
    for (int st = 0; st < 2; st++)
        for (int i = tid; i < 8*64; i += 256){
            int rr = i >> 6, cx = i & 63;
            sB[st][(64+rr)*72 + cx] = __float2bfloat16((rr == 0) ? 1.f : 0.f);
        }

    float acc[2][3][4];
    #pragma unroll
    for (int i = 0; i < 2; i++)
        #pragma unroll
        for (int j = 0; j < 3; j++)
            #pragma unroll
            for (int e = 0; e < 4; e++) acc[i][j][e] = 0.f;

    const __nv_bfloat16* Kb = g_kt + ((size_t)b*CC + h*DD)*TT + sp*(TT/KSPLIT);
    const __nv_bfloat16* Vb = g_vt + ((size_t)b*CC + h*DD)*TT + sp*(TT/KSPLIT);

    auto load_stage = [&](int st, int tc){
        #pragma unroll
        for (int r = 0; r < 2; r++){
            int i = tid + r*256;                 // 512 x 16B per operand
            int row = i >> 3, cq = i & 7;
            CP_ASYNC16(suA[st] + (uint32_t)(row*72 + cq*8)*2,
                       Kb + (size_t)row*TT + tc*64 + cq*8);
            CP_ASYNC16(suB[st] + (uint32_t)(row*72 + cq*8)*2,
                       Vb + (size_t)row*TT + tc*64 + cq*8);
        }
    };

    const int NT = (TT/KSPLIT)/64;   // 16
    load_stage(0, 0); CP_COMMIT();

    for (int tc = 0; tc < NT; tc++){
        const int cur = tc & 1;
        if (tc + 1 < NT){ load_stage(cur^1, tc+1); CP_COMMIT(); CP_WAIT1(); }
        else            { CP_WAIT0(); }
        __syncthreads();

        const __nv_bfloat16* pa = sA[cur];
        const __nv_bfloat16* pb = sB[cur];
        #pragma unroll
        for (int s = 0; s < 4; s++){
            const int kb = s*16 + 2*t4;
            uint32_t ar[2][4], br[3][2];
            #pragma unroll
            for (int mf = 0; mf < 2; mf++){
                int r0 = wm*32 + mf*16 + g;
                ar[mf][0] = lds32(pa +  r0   *72 + kb);
                ar[mf][1] = lds32(pa + (r0+8)*72 + kb);
                ar[mf][2] = lds32(pa +  r0   *72 + kb + 8);
                ar[mf][3] = lds32(pa + (r0+8)*72 + kb + 8);
            }
            #pragma unroll
            for (int nf = 0; nf < 3; nf++){
                if (nf < nt){
                    int c0 = (nf == 2) ? (64 + g) : (wn*16 + nf*8 + g);
                    br[nf][0] = lds32(pb + c0*72 + kb);
                    br[nf][1] = lds32(pb + c0*72 + kb + 8);
                }
            }
            #pragma unroll
            for (int mf = 0; mf < 2; mf++)
                #pragma unroll
                for (int nf = 0; nf < 3; nf++)
                    if (nf < nt) mma_bf16(acc[mf][nf], ar[mf], br[nf]);
        }
        __syncthreads();
    }

    float* dst = g_kvP[sp][bh];
    #pragma unroll
    for (int mf = 0; mf < 2; mf++){
        const int m0 = wm*32 + mf*16 + g;
        #pragma unroll
        for (int nf = 0; nf < 3; nf++){
            if (nf >= nt) continue;
            const int n0 = (nf == 2) ? (64 + 2*t4) : (wn*16 + nf*8 + 2*t4);
            dst[(n0  )*64 + m0    ] = acc[mf][nf][0];
            dst[(n0+1)*64 + m0    ] = acc[mf][nf][1];
            dst[(n0  )*64 + m0 + 8] = acc[mf][nf][2];
            dst[(n0+1)*64 + m0 + 8] = acc[mf][nf][3];
        }
    }
}

// ---------------------------------------------------------------------------
// attn via MMA: per (bh, 128-t chunk): A = q[t][d], B = [kv;ksum][n][d]
// z = column 64; out = acc/(z+1e-6) -> bf16 g_attn16
// ---------------------------------------------------------------------------
__global__ void __launch_bounds__(256) attn_mma_kernel()
{
    __shared__ __nv_bfloat16 sQ[128*72];
    __shared__ __nv_bfloat16 sB[72*72];
    const int blk = blockIdx.x;
    const int tc  = blk % (TT/128);
    const int bh  = blk / (TT/128);
    const int b = bh / HH, h = bh % HH;
    const int tid = threadIdx.x;
    const int wid = tid >> 5, lane = tid & 31;
    const int g = lane >> 2, t4 = lane & 3;
    const uint32_t suQ = smem_u32(sQ);

    // B: sum 4 kv partials, cvt to bf16
    const float* p0 = g_kvP[0][bh];
    const float* p1 = g_kvP[1][bh];
    const float* p2 = g_kvP[2][bh];
    const float* p3 = g_kvP[3][bh];
    for (int i = tid; i < 72*64; i += 256){
        int n = i >> 6, d = i & 63;
        sB[n*72 + d] = __float2bfloat16_rn(p0[i] + p1[i] + p2[i] + p3[i]);
    }

    // A: 128 q rows
    const __nv_bfloat16* Qb = g_q16 + (size_t)(b*TT + tc*128)*CC + h*DD;
    #pragma unroll
    for (int r = 0; r < 4; r++){
        int i = tid + r*256;
        int row = i >> 3, cq = i & 7;
        CP_ASYNC16(suQ + (uint32_t)(row*72 + cq*8)*2, Qb + (size_t)row*CC + cq*8);
    }
    CP_COMMIT(); CP_WAIT0();
    __syncthreads();

    float acc[9][4];
    #pragma unroll
    for (int i = 0; i < 9; i++)
        #pragma unroll
        for (int e = 0; e < 4; e++) acc[i][e] = 0.f;

    const int m0 = wid * 16;
    #pragma unroll
    for (int s = 0; s < 4; s++){
        const int kb = s*16 + 2*t4;
        uint32_t ar[4], br[9][2];
        ar[0] = lds32(sQ + (m0+g  )*72 + kb);
        ar[1] = lds32(sQ + (m0+g+8)*72 + kb);
        ar[2] = lds32(sQ + (m0+g  )*72 + kb + 8);
        ar[3] = lds32(sQ + (m0+g+8)*72 + kb + 8);
        #pragma unroll
        for (int nf = 0; nf < 9; nf++){
            int c0 = nf*8 + g;
            br[nf][0] = lds32(sB + c0*72 + kb);
            br[nf][1] = lds32(sB + c0*72 + kb + 8);
        }
        #pragma unroll
        for (int nf = 0; nf < 9; nf++)
            mma_bf16(acc[nf], ar, br[nf]);
    }

    // z lives at column 64 (ntile 8, t4==0 lanes)
    float zlo = __shfl_sync(0xffffffffu, acc[8][0], lane & ~3);
    float zhi = __shfl_sync(0xffffffffu, acc[8][2], lane & ~3);
    const float rlo = 1.f / (zlo + 1e-6f);
    const float rhi = 1.f / (zhi + 1e-6f);

    const size_t row0 = (size_t)(b*TT + tc*128 + m0 + g);
    #pragma unroll
    for (int nf = 0; nf < 8; nf++){
        const int n0 = h*DD + nf*8 + 2*t4;
        *reinterpret_cast<__nv_bfloat162*>(g_attn16 +  row0     *CC + n0)
            = __floats2bfloat162_rn(acc[nf][0]*rlo, acc[nf][1]*rlo);
        *reinterpret_cast<__nv_bfloat162*>(g_attn16 + (row0 + 8)*CC + n0)
            = __floats2bfloat162_rn(acc[nf][2]*rhi, acc[nf][3]*rhi);
    }
}

// ---------------------------------------------------------------------------
extern "C" void kernel_launch(void* const* d_in, const int* in_sizes, int n_in,
                              void* d_out, int out_size)
{
    const float* x  = (const float*)d_in[0];
    const float* Wq = (const float*)d_in[1];
    const float* bq = (const float*)d_in[2];
    const float* Wk = (const float*)d_in[3];
    const float* bk = (const float*)d_in[4];
    const float* Wv = (const float*)d_in[5];
    const float* bv = (const float*)d_in[6];
    const float* Wo = (const float*)d_in[7];
    const float* bo = (const float*)d_in[8];
    float* out = (float*)d_out;

    __nv_bfloat16 *gxt, *gq, *gkt, *gvt, *gattn, *gw;
    cudaGetSymbolAddress((void**)&gxt,  g_xt);
    cudaGetSymbolAddress((void**)&gq,   g_q16);
    cudaGetSymbolAddress((void**)&gkt,  g_kt);
    cudaGetSymbolAddress((void**)&gvt,  g_vt);
    cudaGetSymbolAddress((void**)&gattn,g_attn16);
    cudaGetSymbolAddress((void**)&gw,   g_w16);

    // 1. pack inputs to bf16
    transpose_round_kernel<<<dim3(TT/32, CC/32, BB), dim3(32,32)>>>(x);
    round_w_kernel<<<CC*CC/256, 256>>>(Wq, gw + 0*(size_t)CC*CC);
    round_w_kernel<<<CC*CC/256, 256>>>(Wk, gw + 1*(size_t)CC*CC);
    round_w_kernel<<<CC*CC/256, 256>>>(Wv, gw + 2*(size_t)CC*CC);
    round_w_kernel<<<CC*CC/256, 256>>>(Wo, gw + 3*(size_t)CC*CC);

    // 2. projections (bf16 tensor cores)
    dim3 gg(BT/128, CC/128);
    gemm_bf16<1><<<gg, 256>>>(gxt, gw + 0*(size_t)CC*CC, bq, nullptr, nullptr, gq);
    gemm_bf16<3><<<gg, 256>>>(gxt, gw + 1*(size_t)CC*CC, bk, nullptr, nullptr, gkt);
    gemm_bf16<4><<<gg, 256>>>(gxt, gw + 2*(size_t)CC*CC, bv, nullptr, nullptr, gvt);

    // 3. linear attention (tensor cores)
    kv_mma_kernel<<<BB*HH*KSPLIT, 256>>>();
    attn_mma_kernel<<<BB*HH*(TT/128), 256>>>();

    // 4. output projection + bias + residual + transpose
    gemm_bf16<2><<<gg, 256>>>(gattn, gw + 3*(size_t)CC*CC, bo, x, out, nullptr);
}

// round 6
// speedup vs baseline: 10.0440x; 1.1916x over previous
#include <cuda_runtime.h>
#include <cuda_bf16.h>
#include <math.h>
#include <stdint.h>

#define BB 4
#define CC 1024
#define TT 4096
#define HH 16
#define DD 64
#define BT (BB*TT)        // 16384
#define KSPLIT 4
#define NKCH 32           // K chunks of 32 per proj GEMM
#define SA 40             // GEMM smem row stride (bf16) — conflict-free for ldmatrix

// ---------------- scratch (alloc-free: __device__ globals) ----------------
__device__ __nv_bfloat16 g_xt [(size_t)BT*CC];     // xt[bt][c]
__device__ __nv_bfloat16 g_q16[(size_t)BT*CC];     // q[bt][c]
__device__ __nv_bfloat16 g_kt [(size_t)BB*CC*TT];  // k^T[b*CC+c][t]
__device__ __nv_bfloat16 g_vt [(size_t)BB*CC*TT];  // v^T[b*CC+c][t]
__device__ __nv_bfloat16 g_attn16[(size_t)BT*CC];  // attn[bt][c]
__device__ __nv_bfloat16 g_w16[(size_t)4*CC*CC];   // Wq,Wk,Wv,Wo bf16
// kv partials: [split][bh][n(72: 0..63=kv cols e, 64=ksum)][d(64)]
__device__ float g_kvP[KSPLIT][BB*HH][72*64];

// ---------------- helpers ----------------
__device__ __forceinline__ uint32_t smem_u32(const void* p){
    uint32_t a;
    asm("{ .reg .u64 t; cvta.to.shared.u64 t, %1; cvt.u32.u64 %0, t; }" : "=r"(a) : "l"(p));
    return a;
}

#define CP_ASYNC16(saddr, gptr) \
    asm volatile("cp.async.cg.shared.global [%0], [%1], 16;" :: "r"(saddr), "l"(gptr))
#define CP_COMMIT() asm volatile("cp.async.commit_group;" ::: "memory")
#define CP_WAIT1()  asm volatile("cp.async.wait_group 1;" ::: "memory")
#define CP_WAIT0()  asm volatile("cp.async.wait_group 0;" ::: "memory")

// m16n8k16 bf16: D += A(16x16,row) * B(16x8, stored [n][k], k contiguous)
__device__ __forceinline__ void mma_bf16(float* c, const uint32_t* a, const uint32_t* b){
    asm volatile("mma.sync.aligned.m16n8k16.row.col.f32.bf16.bf16.f32 "
        "{%0,%1,%2,%3}, {%4,%5,%6,%7}, {%8,%9}, {%0,%1,%2,%3};"
        : "+f"(c[0]), "+f"(c[1]), "+f"(c[2]), "+f"(c[3])
        : "r"(a[0]), "r"(a[1]), "r"(a[2]), "r"(a[3]), "r"(b[0]), "r"(b[1]));
}
__device__ __forceinline__ uint32_t lds32(const __nv_bfloat16* p){
    return *reinterpret_cast<const uint32_t*>(p);
}
__device__ __forceinline__ void ldsm_x4(uint32_t* r, uint32_t addr){
    asm volatile("ldmatrix.sync.aligned.m8n8.x4.shared.b16 {%0,%1,%2,%3}, [%4];"
        : "=r"(r[0]), "=r"(r[1]), "=r"(r[2]), "=r"(r[3]) : "r"(addr));
}

// ---------------------------------------------------------------------------
// bf16 tensor-core GEMM v2: D[m,n] = sum_k A[m,k]*Bw[n,k]
// block 128x128, 4 warps (2x2), warp tile 64x64, 3-stage cp.async, ldmatrix.
// MODE 1: Q : elu(D+bias)+1 -> bf16 out16[m][CC]
// MODE 3: K : elu(D+bias)+1 -> bf16 transposed out16[(b*CC+n)*TT + t]
// MODE 4: V : D+bias        -> bf16 transposed
// MODE 2: O : D+bias+resid  -> fp32 outf[b][n][t]
// ---------------------------------------------------------------------------
#define STG (128*SA)                 // bf16 elements per operand per stage
#define GEMM_SMEM (3*2*STG*2)        // bytes = 61440

template<int MODE>
__global__ void __launch_bounds__(128, 2)
gemm_bf16(const __nv_bfloat16* __restrict__ A, const __nv_bfloat16* __restrict__ Bw,
          const float* __restrict__ bias, const float* __restrict__ resid,
          float* __restrict__ outf, __nv_bfloat16* __restrict__ out16)
{
    extern __shared__ __nv_bfloat16 sm[];
    const uint32_t su = smem_u32(sm);
    const int tid  = threadIdx.x;
    const int wid  = tid >> 5, lane = tid & 31;
    const int g    = lane >> 2, t4 = lane & 3;
    const int wm   = wid >> 1,  wn  = wid & 1;
    const int bm   = blockIdx.x * 128;
    const int bn   = blockIdx.y * 128;

    const __nv_bfloat16* Ab = A  + (size_t)bm * CC;
    const __nv_bfloat16* Bb = Bw + (size_t)bn * CC;

    float acc[4][8][4];
    #pragma unroll
    for (int i = 0; i < 4; i++)
        #pragma unroll
        for (int j = 0; j < 8; j++)
            #pragma unroll
            for (int e = 0; e < 4; e++) acc[i][j][e] = 0.f;

    // per-lane ldmatrix address components
    const int rowA_l = (lane & 7) + 8*((lane >> 3) & 1);
    const int colA_l = 8*(lane >> 4);
    const int rowB_l = (lane & 7) + 8*(lane >> 4);
    const int colB_l = 8*((lane >> 3) & 1);

    auto load_stage = [&](int st, int kc){
        const uint32_t sa = su + (uint32_t)(st*2*STG)*2;
        const uint32_t sb = sa + (uint32_t)STG*2;
        const __nv_bfloat16* a = Ab + kc*32;
        const __nv_bfloat16* b = Bb + kc*32;
        #pragma unroll
        for (int r = 0; r < 4; r++){
            int i = tid + r*128;            // 512 x 16B per operand
            int row = i >> 2, cq = i & 3;
            CP_ASYNC16(sa + (uint32_t)(row*SA + cq*8)*2, a + (size_t)row*CC + cq*8);
            CP_ASYNC16(sb + (uint32_t)(row*SA + cq*8)*2, b + (size_t)row*CC + cq*8);
        }
        CP_COMMIT();
    };

    load_stage(0, 0);
    load_stage(1, 1);

    for (int kc = 0; kc < NKCH; kc++){
        if (kc + 1 < NKCH) { CP_WAIT1(); } else { CP_WAIT0(); }
        __syncthreads();
        if (kc + 2 < NKCH) load_stage((kc+2) % 3, kc+2);

        const int st = kc % 3;
        const uint32_t sa = su + (uint32_t)(st*2*STG)*2;
        const uint32_t sb = sa + (uint32_t)STG*2;
        #pragma unroll
        for (int s = 0; s < 2; s++){
            const int sk = s*16;
            uint32_t ar[4][4], br[4][4];
            #pragma unroll
            for (int mf = 0; mf < 4; mf++){
                int ml = wm*64 + mf*16;
                ldsm_x4(ar[mf], sa + (uint32_t)((ml + rowA_l)*SA + sk + colA_l)*2);
            }
            #pragma unroll
            for (int nf2 = 0; nf2 < 4; nf2++){
                int nl = wn*64 + nf2*16;
                ldsm_x4(br[nf2], sb + (uint32_t)((nl + rowB_l)*SA + sk + colB_l)*2);
            }
            #pragma unroll
            for (int mf = 0; mf < 4; mf++)
                #pragma unroll
                for (int nf = 0; nf < 8; nf++)
                    mma_bf16(acc[mf][nf], ar[mf], &br[nf >> 1][(nf & 1)*2]);
        }
    }

    // ---- epilogue ----
    #pragma unroll
    for (int mf = 0; mf < 4; mf++){
        const int m0 = bm + wm*64 + mf*16 + g;
        #pragma unroll
        for (int nf = 0; nf < 8; nf++){
            const int n0 = bn + wn*64 + nf*8 + t4*2;
            const float b0 = bias[n0], b1 = bias[n0+1];
            float v00 = acc[mf][nf][0] + b0;
            float v01 = acc[mf][nf][1] + b1;
            float v10 = acc[mf][nf][2] + b0;
            float v11 = acc[mf][nf][3] + b1;
            if (MODE == 1 || MODE == 3){
                v00 = (v00 > 0.f) ? (v00 + 1.f) : expf(v00);
                v01 = (v01 > 0.f) ? (v01 + 1.f) : expf(v01);
                v10 = (v10 > 0.f) ? (v10 + 1.f) : expf(v10);
                v11 = (v11 > 0.f) ? (v11 + 1.f) : expf(v11);
            }
            if (MODE == 1){
                *reinterpret_cast<__nv_bfloat162*>(out16 + (size_t) m0   *CC + n0)
                    = __floats2bfloat162_rn(v00, v01);
                *reinterpret_cast<__nv_bfloat162*>(out16 + (size_t)(m0+8)*CC + n0)
                    = __floats2bfloat162_rn(v10, v11);
            } else if (MODE == 3 || MODE == 4){
                const int b = m0 / TT, t = m0 % TT;
                size_t r0i = ((size_t)b*CC + n0)*TT + t;
                size_t r1i = r0i + TT;
                out16[r0i]     = __float2bfloat16_rn(v00);
                out16[r1i]     = __float2bfloat16_rn(v01);
                out16[r0i + 8] = __float2bfloat16_rn(v10);
                out16[r1i + 8] = __float2bfloat16_rn(v11);
            } else { // MODE 2
                const int b = m0 / TT, t = m0 % TT;
                size_t i00 = (size_t)b*CC*TT + (size_t)n0*TT + t;
                size_t i01 = i00 + TT;
                outf[i00]     = v00 + resid[i00];
                outf[i01]     = v01 + resid[i01];
                outf[i00 + 8] = v10 + resid[i00 + 8];
                outf[i01 + 8] = v11 + resid[i01 + 8];
            }
        }
    }
}

// ---------------------------------------------------------------------------
// x[b,c,t] -> g_xt[b*T+t][c] bf16
// ---------------------------------------------------------------------------
__global__ void transpose_round_kernel(const float* __restrict__ x)
{
    __shared__ float tile[32][33];
    const int t0 = blockIdx.x * 32;
    const int c0 = blockIdx.y * 32;
    const int b  = blockIdx.z;
    const int tx = threadIdx.x, ty = threadIdx.y;
    tile[ty][tx] = x[(size_t)b*CC*TT + (size_t)(c0+ty)*TT + t0 + tx];
    __syncthreads();
    g_xt[(size_t)(b*TT + t0 + ty)*CC + c0 + tx] = __float2bfloat16_rn(tile[tx][ty]);
}

// all 4 weights in one launch: blockIdx.y selects the matrix
__global__ void round_w4_kernel(const float* __restrict__ w0, const float* __restrict__ w1,
                                const float* __restrict__ w2, const float* __restrict__ w3,
                                __nv_bfloat16* __restrict__ dst)
{
    const float* w = (blockIdx.y == 0) ? w0 : (blockIdx.y == 1) ? w1
                   : (blockIdx.y == 2) ? w2 : w3;
    int i = blockIdx.x * 256 + threadIdx.x;
    dst[(size_t)blockIdx.y*CC*CC + i] = __float2bfloat16_rn(w[i]);
}

// ---------------------------------------------------------------------------
// kv via MMA: per (bh, split): A = k^T[d][t], B = [v^T; ones][n][t]
// ---------------------------------------------------------------------------
__global__ void __launch_bounds__(256) kv_mma_kernel()
{
    __shared__ __nv_bfloat16 sA[2][64*72];
    __shared__ __nv_bfloat16 sB[2][72*72];
    const int blk = blockIdx.x;
    const int sp  = blk % KSPLIT;
    const int bh  = blk / KSPLIT;
    const int b = bh / HH, h = bh % HH;
    const int tid = threadIdx.x;
    const int wid = tid >> 5, lane = tid & 31;
    const int g = lane >> 2, t4 = lane & 3;
    const int wm = wid >> 2, wn = wid & 3;
    const int nt = (wn == 3) ? 3 : 2;

    const uint32_t suA[2] = {smem_u32(sA[0]), smem_u32(sA[1])};
    const uint32_t suB[2] = {smem_u32(sB[0]), smem_u32(sB[1])};

    for (int st = 0; st < 2; st++)
        for (int i = tid; i < 8*64; i += 256){
            int rr = i >> 6, cx = i & 63;
            sB[st][(64+rr)*72 + cx] = __float2bfloat16((rr == 0) ? 1.f : 0.f);
        }

    float acc[2][3][4];
    #pragma unroll
    for (int i = 0; i < 2; i++)
        #pragma unroll
        for (int j = 0; j < 3; j++)
            #pragma unroll
            for (int e = 0; e < 4; e++) acc[i][j][e] = 0.f;

    const __nv_bfloat16* Kb = g_kt + ((size_t)b*CC + h*DD)*TT + sp*(TT/KSPLIT);
    const __nv_bfloat16* Vb = g_vt + ((size_t)b*CC + h*DD)*TT + sp*(TT/KSPLIT);

    auto load_stage = [&](int st, int tc){
        #pragma unroll
        for (int r = 0; r < 2; r++){
            int i = tid + r*256;
            int row = i >> 3, cq = i & 7;
            CP_ASYNC16(suA[st] + (uint32_t)(row*72 + cq*8)*2,
                       Kb + (size_t)row*TT + tc*64 + cq*8);
            CP_ASYNC16(suB[st] + (uint32_t)(row*72 + cq*8)*2,
                       Vb + (size_t)row*TT + tc*64 + cq*8);
        }
    };

    const int NT = (TT/KSPLIT)/64;   // 16
    load_stage(0, 0); CP_COMMIT();

    for (int tc = 0; tc < NT; tc++){
        const int cur = tc & 1;
        if (tc + 1 < NT){ load_stage(cur^1, tc+1); CP_COMMIT(); CP_WAIT1(); }
        else            { CP_WAIT0(); }
        __syncthreads();

        const __nv_bfloat16* pa = sA[cur];
        const __nv_bfloat16* pb = sB[cur];
        #pragma unroll
        for (int s = 0; s < 4; s++){
            const int kb = s*16 + 2*t4;
            uint32_t ar[2][4], br[3][2];
            #pragma unroll
            for (int mf = 0; mf < 2; mf++){
                int r0 = wm*32 + mf*16 + g;
                ar[mf][0] = lds32(pa +  r0   *72 + kb);
                ar[mf][1] = lds32(pa + (r0+8)*72 + kb);
                ar[mf][2] = lds32(pa +  r0   *72 + kb + 8);
                ar[mf][3] = lds32(pa + (r0+8)*72 + kb + 8);
            }
            #pragma unroll
            for (int nf = 0; nf < 3; nf++){
                if (nf < nt){
                    int c0 = (nf == 2) ? (64 + g) : (wn*16 + nf*8 + g);
                    br[nf][0] = lds32(pb + c0*72 + kb);
                    br[nf][1] = lds32(pb + c0*72 + kb + 8);
                }
            }
            #pragma unroll
            for (int mf = 0; mf < 2; mf++)
                #pragma unroll
                for (int nf = 0; nf < 3; nf++)
                    if (nf < nt) mma_bf16(acc[mf][nf], ar[mf], br[nf]);
        }
        __syncthreads();
    }

    float* dst = g_kvP[sp][bh];
    #pragma unroll
    for (int mf = 0; mf < 2; mf++){
        const int m0 = wm*32 + mf*16 + g;
        #pragma unroll
        for (int nf = 0; nf < 3; nf++){
            if (nf >= nt) continue;
            const int n0 = (nf == 2) ? (64 + 2*t4) : (wn*16 + nf*8 + 2*t4);
            dst[(n0  )*64 + m0    ] = acc[mf][nf][0];
            dst[(n0+1)*64 + m0    ] = acc[mf][nf][1];
            dst[(n0  )*64 + m0 + 8] = acc[mf][nf][2];
            dst[(n0+1)*64 + m0 + 8] = acc[mf][nf][3];
        }
    }
}

// ---------------------------------------------------------------------------
// attn via MMA: per (bh, 128-t chunk): A = q[t][d], B = [kv;ksum][n][d]
// ---------------------------------------------------------------------------
__global__ void __launch_bounds__(256) attn_mma_kernel()
{
    __shared__ __nv_bfloat16 sQ[128*72];
    __shared__ __nv_bfloat16 sB[72*72];
    const int blk = blockIdx.x;
    const int tc  = blk % (TT/128);
    const int bh  = blk / (TT/128);
    const int b = bh / HH, h = bh % HH;
    const int tid = threadIdx.x;
    const int wid = tid >> 5, lane = tid & 31;
    const int g = lane >> 2, t4 = lane & 3;
    const uint32_t suQ = smem_u32(sQ);

    const float* p0 = g_kvP[0][bh];
    const float* p1 = g_kvP[1][bh];
    const float* p2 = g_kvP[2][bh];
    const float* p3 = g_kvP[3][bh];
    for (int i = tid; i < 72*64; i += 256){
        int n = i >> 6, d = i & 63;
        sB[n*72 + d] = __float2bfloat16_rn(p0[i] + p1[i] + p2[i] + p3[i]);
    }

    const __nv_bfloat16* Qb = g_q16 + (size_t)(b*TT + tc*128)*CC + h*DD;
    #pragma unroll
    for (int r = 0; r < 4; r++){
        int i = tid + r*256;
        int row = i >> 3, cq = i & 7;
        CP_ASYNC16(suQ + (uint32_t)(row*72 + cq*8)*2, Qb + (size_t)row*CC + cq*8);
    }
    CP_COMMIT(); CP_WAIT0();
    __syncthreads();

    float acc[9][4];
    #pragma unroll
    for (int i = 0; i < 9; i++)
        #pragma unroll
        for (int e = 0; e < 4; e++) acc[i][e] = 0.f;

    const int m0 = wid * 16;
    #pragma unroll
    for (int s = 0; s < 4; s++){
        const int kb = s*16 + 2*t4;
        uint32_t ar[4], br[9][2];
        ar[0] = lds32(sQ + (m0+g  )*72 + kb);
        ar[1] = lds32(sQ + (m0+g+8)*72 + kb);
        ar[2] = lds32(sQ + (m0+g  )*72 + kb + 8);
        ar[3] = lds32(sQ + (m0+g+8)*72 + kb + 8);
        #pragma unroll
        for (int nf = 0; nf < 9; nf++){
            int c0 = nf*8 + g;
            br[nf][0] = lds32(sB + c0*72 + kb);
            br[nf][1] = lds32(sB + c0*72 + kb + 8);
        }
        #pragma unroll
        for (int nf = 0; nf < 9; nf++)
            mma_bf16(acc[nf], ar, br[nf]);
    }

    float zlo = __shfl_sync(0xffffffffu, acc[8][0], lane & ~3);
    float zhi = __shfl_sync(0xffffffffu, acc[8][2], lane & ~3);
    const float rlo = 1.f / (zlo + 1e-6f);
    const float rhi = 1.f / (zhi + 1e-6f);

    const size_t row0 = (size_t)(b*TT + tc*128 + m0 + g);
    #pragma unroll
    for (int nf = 0; nf < 8; nf++){
        const int n0 = h*DD + nf*8 + 2*t4;
        *reinterpret_cast<__nv_bfloat162*>(g_attn16 +  row0     *CC + n0)
            = __floats2bfloat162_rn(acc[nf][0]*rlo, acc[nf][1]*rlo);
        *reinterpret_cast<__nv_bfloat162*>(g_attn16 + (row0 + 8)*CC + n0)
            = __floats2bfloat162_rn(acc[nf][2]*rhi, acc[nf][3]*rhi);
    }
}

// ---------------------------------------------------------------------------
extern "C" void kernel_launch(void* const* d_in, const int* in_sizes, int n_in,
                              void* d_out, int out_size)
{
    const float* x  = (const float*)d_in[0];
    const float* Wq = (const float*)d_in[1];
    const float* bq = (const float*)d_in[2];
    const float* Wk = (const float*)d_in[3];
    const float* bk = (const float*)d_in[4];
    const float* Wv = (const float*)d_in[5];
    const float* bv = (const float*)d_in[6];
    const float* Wo = (const float*)d_in[7];
    const float* bo = (const float*)d_in[8];
    float* out = (float*)d_out;

    __nv_bfloat16 *gxt, *gq, *gkt, *gvt, *gattn, *gw;
    cudaGetSymbolAddress((void**)&gxt,  g_xt);
    cudaGetSymbolAddress((void**)&gq,   g_q16);
    cudaGetSymbolAddress((void**)&gkt,  g_kt);
    cudaGetSymbolAddress((void**)&gvt,  g_vt);
    cudaGetSymbolAddress((void**)&gattn,g_attn16);
    cudaGetSymbolAddress((void**)&gw,   g_w16);

    cudaFuncSetAttribute(gemm_bf16<1>, cudaFuncAttributeMaxDynamicSharedMemorySize, GEMM_SMEM);
    cudaFuncSetAttribute(gemm_bf16<2>, cudaFuncAttributeMaxDynamicSharedMemorySize, GEMM_SMEM);
    cudaFuncSetAttribute(gemm_bf16<3>, cudaFuncAttributeMaxDynamicSharedMemorySize, GEMM_SMEM);
    cudaFuncSetAttribute(gemm_bf16<4>, cudaFuncAttributeMaxDynamicSharedMemorySize, GEMM_SMEM);

    // 1. pack inputs to bf16
    transpose_round_kernel<<<dim3(TT/32, CC/32, BB), dim3(32,32)>>>(x);
    round_w4_kernel<<<dim3(CC*CC/256, 4), 256>>>(Wq, Wk, Wv, Wo, gw);

    // 2. projections (bf16 tensor cores, 64x64 warp tiles + ldmatrix)
    dim3 gg(BT/128, CC/128);
    gemm_bf16<1><<<gg, 128, GEMM_SMEM>>>(gxt, gw + 0*(size_t)CC*CC, bq, nullptr, nullptr, gq);
    gemm_bf16<3><<<gg, 128, GEMM_SMEM>>>(gxt, gw + 1*(size_t)CC*CC, bk, nullptr, nullptr, gkt);
    gemm_bf16<4><<<gg, 128, GEMM_SMEM>>>(gxt, gw + 2*(size_t)CC*CC, bv, nullptr, nullptr, gvt);

    // 3. linear attention (tensor cores)
    kv_mma_kernel<<<BB*HH*KSPLIT, 256>>>();
    attn_mma_kernel<<<BB*HH*(TT/128), 256>>>();

    // 4. output projection + bias + residual + transpose
    gemm_bf16<2><<<gg, 128, GEMM_SMEM>>>(gattn, gw + 3*(size_t)CC*CC, bo, x, out, nullptr);
}